// round 9
// baseline (speedup 1.0000x reference)
#include <cuda_runtime.h>

#define BB    128
#define DX    1024
#define NKK   1024
#define DKIN  512
#define NH    16
#define DKH   64
#define HD    1024
#define DOUT  512

// ---------------- scratch (device globals; 16B aligned) ----------------
__device__ __align__(16) float g_ksum[BB * DKIN];
__device__ __align__(16) float g_s1[DX], g_t1[DX];     // bn1 affine fold
__device__ __align__(16) float g_xq[BB * HD];
__device__ __align__(16) float g_s2[DKH], g_t2a[DKH];  // bn2 affine fold
__device__ __align__(16) float g_Wck[DOUT * DKIN];     // Wo @ Wk  (512x512)
__device__ __align__(16) float g_Wc[DOUT * HD];        // Wo . blockdiag(Wlin^T)
__device__ __align__(16) float g_bias2[DOUT], g_bias3[DOUT];

// =====================================================================
// 128x32 GEMM tile, double-buffered: C[128, n0..n0+32) += A[128,Kchunk] @ W^T
// 256 threads, 4x4 accum/thread, BK=16, atomicAdd epilogue.
// MODE: 0 none; 1 per-col affine (idx = col-kStart, kLen<=128); 2 idx = col&63
template <int MODE>
__device__ __forceinline__ void gemm128(
    const float* __restrict__ A, int lda,
    const float* __restrict__ W, int ldw,
    float* __restrict__ C, int ldc,
    int n0, int kStart, int nIter,
    const float* __restrict__ gsc, const float* __restrict__ gsh)
{
    __shared__ float As[2][16][132];
    __shared__ float Ws[2][16][36];
    __shared__ float ssc[128], ssh[128];
    const int t = threadIdx.x;
    if (MODE == 1) { if (t < 128) { ssc[t] = gsc[kStart + t]; ssh[t] = gsh[kStart + t]; } }
    if (MODE == 2) { if (t < 64)  { ssc[t] = gsc[t];          ssh[t] = gsh[t]; } }
    if (MODE) __syncthreads();

    const int rowA = t & 127, kgA = t >> 7;   // kgA in {0,1}; second load uses kgA+2
    const int nW = t & 31, kgW = t >> 5;      // valid for t<128
    const int ty = t >> 3, tx = t & 7;

    float4 ra0, ra1, rw;
    {
        int k0 = kStart;
        ra0 = *(const float4*)&A[(size_t)rowA * lda + k0 + kgA * 4];
        ra1 = *(const float4*)&A[(size_t)rowA * lda + k0 + (kgA + 2) * 4];
        if (t < 128) rw = *(const float4*)&W[(size_t)(n0 + nW) * ldw + k0 + kgW * 4];
        float va[8] = {ra0.x, ra0.y, ra0.z, ra0.w, ra1.x, ra1.y, ra1.z, ra1.w};
        #pragma unroll
        for (int u = 0; u < 2; u++) {
            int kg = kgA + u * 2;
            #pragma unroll
            for (int j = 0; j < 4; j++) {
                float v = va[u * 4 + j];
                if (MODE == 1) { int ci = kg * 4 + j;              v = v * ssc[ci] + ssh[ci]; }
                if (MODE == 2) { int ci = (k0 + kg * 4 + j) & 63;  v = v * ssc[ci] + ssh[ci]; }
                As[0][kg * 4 + j][rowA] = v;
            }
        }
        if (t < 128) {
            Ws[0][kgW * 4 + 0][nW] = rw.x; Ws[0][kgW * 4 + 1][nW] = rw.y;
            Ws[0][kgW * 4 + 2][nW] = rw.z; Ws[0][kgW * 4 + 3][nW] = rw.w;
        }
    }
    __syncthreads();

    float acc[4][4] = {};
    for (int it = 0; it < nIter; it++) {
        const int buf = it & 1;
        float4 na0, na1, nw;
        const bool more = (it + 1 < nIter);
        if (more) {
            int kn = kStart + (it + 1) * 16;
            na0 = *(const float4*)&A[(size_t)rowA * lda + kn + kgA * 4];
            na1 = *(const float4*)&A[(size_t)rowA * lda + kn + (kgA + 2) * 4];
            if (t < 128) nw = *(const float4*)&W[(size_t)(n0 + nW) * ldw + kn + kgW * 4];
        }
        #pragma unroll
        for (int kk = 0; kk < 16; kk++) {
            float4 a = *(const float4*)&As[buf][kk][ty * 4];
            float4 b = *(const float4*)&Ws[buf][kk][tx * 4];
            acc[0][0] += a.x * b.x; acc[0][1] += a.x * b.y; acc[0][2] += a.x * b.z; acc[0][3] += a.x * b.w;
            acc[1][0] += a.y * b.x; acc[1][1] += a.y * b.y; acc[1][2] += a.y * b.z; acc[1][3] += a.y * b.w;
            acc[2][0] += a.z * b.x; acc[2][1] += a.z * b.y; acc[2][2] += a.z * b.z; acc[2][3] += a.z * b.w;
            acc[3][0] += a.w * b.x; acc[3][1] += a.w * b.y; acc[3][2] += a.w * b.z; acc[3][3] += a.w * b.w;
        }
        if (more) {
            int kn = kStart + (it + 1) * 16;
            int nb = buf ^ 1;
            float va[8] = {na0.x, na0.y, na0.z, na0.w, na1.x, na1.y, na1.z, na1.w};
            #pragma unroll
            for (int u = 0; u < 2; u++) {
                int kg = kgA + u * 2;
                #pragma unroll
                for (int j = 0; j < 4; j++) {
                    float v = va[u * 4 + j];
                    if (MODE == 1) { int ci = (kn - kStart) + kg * 4 + j; v = v * ssc[ci] + ssh[ci]; }
                    if (MODE == 2) { int ci = (kn + kg * 4 + j) & 63;     v = v * ssc[ci] + ssh[ci]; }
                    As[nb][kg * 4 + j][rowA] = v;
                }
            }
            if (t < 128) {
                Ws[nb][kgW * 4 + 0][nW] = nw.x; Ws[nb][kgW * 4 + 1][nW] = nw.y;
                Ws[nb][kgW * 4 + 2][nW] = nw.z; Ws[nb][kgW * 4 + 3][nW] = nw.w;
            }
            __syncthreads();
        }
    }
    #pragma unroll
    for (int i = 0; i < 4; i++)
        #pragma unroll
        for (int j = 0; j < 4; j++)
            atomicAdd(&C[(size_t)(ty * 4 + i) * ldc + n0 + tx * 4 + j], acc[i][j]);
}

// =====================================================================
// classic 64x64 tile, C[m0.., n0C..] (+)= A[M,K]@B[K,N] chunk
template <bool ATOMIC>
__device__ __forceinline__ void gemm64(
    const float* __restrict__ A, int lda,   // A[M,K], K contiguous
    const float* __restrict__ B, int ldb,   // B[K,N], N contiguous
    float* __restrict__ C, int ldc,
    int m0, int n0B, int n0C, int kStart, int kLen)
{
    __shared__ float As[16][68];
    __shared__ float Bs[16][68];
    int t = threadIdx.x;
    int ty = t >> 4, tx = t & 15;
    float acc[4][4] = {};
    for (int k0 = kStart; k0 < kStart + kLen; k0 += 16) {
        {
            int m = t & 63, kg = t >> 6;
            float4 a = *(const float4*)&A[(size_t)(m0 + m) * lda + k0 + kg * 4];
            As[kg * 4 + 0][m] = a.x; As[kg * 4 + 1][m] = a.y;
            As[kg * 4 + 2][m] = a.z; As[kg * 4 + 3][m] = a.w;
        }
        {
            int n4 = t & 15, kk = t >> 4;
            float4 b = *(const float4*)&B[(size_t)(k0 + kk) * ldb + n0B + n4 * 4];
            *(float4*)&Bs[kk][n4 * 4] = b;
        }
        __syncthreads();
        #pragma unroll
        for (int kk = 0; kk < 16; kk++) {
            float4 a = *(const float4*)&As[kk][ty * 4];
            float4 b = *(const float4*)&Bs[kk][tx * 4];
            acc[0][0] += a.x * b.x; acc[0][1] += a.x * b.y; acc[0][2] += a.x * b.z; acc[0][3] += a.x * b.w;
            acc[1][0] += a.y * b.x; acc[1][1] += a.y * b.y; acc[1][2] += a.y * b.z; acc[1][3] += a.y * b.w;
            acc[2][0] += a.z * b.x; acc[2][1] += a.z * b.y; acc[2][2] += a.z * b.z; acc[2][3] += a.z * b.w;
            acc[3][0] += a.w * b.x; acc[3][1] += a.w * b.y; acc[3][2] += a.w * b.z; acc[3][3] += a.w * b.w;
        }
        __syncthreads();
    }
    #pragma unroll
    for (int i = 0; i < 4; i++)
        #pragma unroll
        for (int j = 0; j < 4; j++) {
            float* p = &C[(size_t)(m0 + ty * 4 + i) * ldc + n0C + tx * 4 + j];
            if (ATOMIC) atomicAdd(p, acc[i][j]); else *p = acc[i][j];
        }
}

// =====================================================================
// K0: bn1 stats + bias vectors + zero/bias inits.  grid = 608 x 256
__global__ void k0_kernel(const float* __restrict__ x,
                          const float* __restrict__ bn1g, const float* __restrict__ bn1b,
                          const float* __restrict__ Wo,
                          const float* __restrict__ bk, const float* __restrict__ blin,
                          const float* __restrict__ bo, const float* __restrict__ bx)
{
    int blk = blockIdx.x, t = threadIdx.x;
    if (blk < 32) {
        __shared__ float ss[8][32], sq[8][32];
        int c = t & 31, r = t >> 5;
        int col = blk * 32 + c;
        float s = 0.f, q = 0.f;
        for (int i = r; i < BB; i += 8) {
            float v = x[(size_t)i * DX + col];
            s += v; q += v * v;
        }
        ss[r][c] = s; sq[r][c] = q;
        __syncthreads();
        if (r == 0) {
            float S = 0.f, Q = 0.f;
            #pragma unroll
            for (int i = 0; i < 8; i++) { S += ss[i][c]; Q += sq[i][c]; }
            float m = S * (1.f / BB);
            float var = Q * (1.f / BB) - m * m;
            float sc = rsqrtf(var + 1e-5f) * bn1g[col];
            g_s1[col] = sc;
            g_t1[col] = bn1b[col] - m * sc;
        }
    } else if (blk < 160) {
        // bias2 = NK*(Wo@bk)+bo ; bias3 = Wo@blin_ext+bo  (one warp per output)
        int wid = (blk - 32) * 8 + (t >> 5), lane = t & 31;
        int o = wid & 511;
        const float* wrow = Wo + (size_t)o * HD;
        float s = 0.f;
        if (wid < 512) {
            for (int j = lane; j < HD; j += 32) s += wrow[j] * bk[j];
        } else {
            for (int j = lane; j < HD; j += 32) s += wrow[j] * blin[j & 63];
        }
        #pragma unroll
        for (int off = 16; off > 0; off >>= 1) s += __shfl_xor_sync(0xffffffffu, s, off);
        if (lane == 0) {
            if (wid < 512) g_bias2[o] = (float)NKK * s + bo[o];
            else           g_bias3[o] = s + bo[o];
        }
    } else if (blk < 288) {
        ((float4*)g_xq)[(size_t)(blk - 160) * 256 + t] = ((const float4*)bx)[t];
    } else if (blk < 352) {
        ((float4*)g_ksum)[(size_t)(blk - 288) * 256 + t] = make_float4(0.f, 0.f, 0.f, 0.f);
    } else {
        ((float4*)g_Wck)[(size_t)(blk - 352) * 256 + t] = make_float4(0.f, 0.f, 0.f, 0.f);
    }
}

// =====================================================================
// K1: HBM-bound ksum + xq GEMM + Wck GEMM + Wc + fills.  grid = 2816 x 256
__global__ void __launch_bounds__(256, 4)
k1_kernel(const float* __restrict__ x, const float* __restrict__ k,
          const float* __restrict__ Wx, const float* __restrict__ Wk,
          const float* __restrict__ Wlin, const float* __restrict__ Wo,
          float4* __restrict__ attn_out,
          float* __restrict__ out2, float* __restrict__ out3)
{
    int blk = blockIdx.x, t = threadIdx.x;
    int ksumIdx = (blk < 512) ? blk : ((blk >= 768 && blk < 1280) ? blk - 256 : -1);
    if (ksumIdx >= 0) {
        // ---- ksum partial (128 n-rows) -> REDG into g_ksum ----
        int b = ksumIdx >> 3, chunk = ksumIdx & 7;
        int c4 = t & 127, h = t >> 7;
        const float4* kp = (const float4*)(k + (size_t)b * NKK * DKIN
                                             + (size_t)chunk * 128 * DKIN);
        float4 acc = make_float4(0.f, 0.f, 0.f, 0.f);
        int base = h * 64;
        #pragma unroll 8
        for (int n = 0; n < 64; n++) {
            float4 v = kp[(size_t)(base + n) * (DKIN / 4) + c4];
            acc.x += v.x; acc.y += v.y; acc.z += v.z; acc.w += v.w;
        }
        __shared__ float4 sbuf[128];
        if (h) sbuf[c4] = acc;
        __syncthreads();
        if (!h) {
            float4 o = sbuf[c4];
            float* dst = &g_ksum[(size_t)b * DKIN + c4 * 4];
            atomicAdd(dst + 0, acc.x + o.x); atomicAdd(dst + 1, acc.y + o.y);
            atomicAdd(dst + 2, acc.z + o.z); atomicAdd(dst + 3, acc.w + o.w);
        }
    } else if (blk < 768) {
        // ---- xq += bn1(x) @ Wx^T : 32 stripes x splitK 8 (chunk 128) = 256 blocks ----
        int id = blk - 512;
        int n0 = (id & 31) * 32, s = id >> 5;
        gemm128<1>(x, DX, Wx, DX, g_xq, HD, n0, s * 128, 8, g_s1, g_t1);
    } else if (blk < 1536) {
        // ---- Wck = Wo(512,1024) @ Wk(1024,512) : 64 tiles x splitK 4 (chunk 256) ----
        int id = blk - 1280;
        int s = id >> 6, tile = id & 63;
        gemm64<true>(Wo, HD, Wk, DKIN, g_Wck, DKIN,
                     (tile >> 3) * 64, (tile & 7) * 64, (tile & 7) * 64, s * 256, 256);
    } else if (blk < 1664) {
        // ---- Wc: per-head Wo[:,h*64:] (512x64) @ Wlin (64x64) : 128 blocks ----
        int id = blk - 1536;
        int h = id >> 3, ms = id & 7;
        gemm64<false>(Wo + h * 64, HD, Wlin, DKH, g_Wc, HD, ms * 64, 0, h * 64, 0, 64);
    } else if (blk < 2688) {
        // ---- attn output = all ones ----
        size_t base = (size_t)(blk - 1664) * 512 + t * 2;
        float4 one = make_float4(1.f, 1.f, 1.f, 1.f);
        attn_out[base] = one; attn_out[base + 1] = one;
    } else {
        // ---- out2/out3 bias init ----
        int idx = (blk - 2688) * 1024 + t * 4;
        if (idx < BB * DOUT) {
            *(float4*)&out2[idx] = *(const float4*)&g_bias2[idx & (DOUT - 1)];
        } else {
            int i2 = idx - BB * DOUT;
            *(float4*)&out3[i2] = *(const float4*)&g_bias3[i2 & (DOUT - 1)];
        }
    }
}

// =====================================================================
// K2: bn2 stats only.  grid = 64 x 256
__global__ void k2_kernel(const float* __restrict__ bn2g, const float* __restrict__ bn2b)
{
    __shared__ float ss[256], sq[256];
    int d = blockIdx.x, t = threadIdx.x;
    float s = 0.f, q = 0.f;
    for (int i = t; i < BB * NH; i += 256) {
        int b = i >> 4, h = i & 15;
        float v = g_xq[(size_t)b * HD + h * DKH + d];
        s += v; q += v * v;
    }
    ss[t] = s; sq[t] = q;
    __syncthreads();
    for (int o = 128; o > 0; o >>= 1) {
        if (t < o) { ss[t] += ss[t + o]; sq[t] += sq[t + o]; }
        __syncthreads();
    }
    if (t == 0) {
        float m = ss[0] * (1.f / (BB * NH));
        float var = sq[0] * (1.f / (BB * NH)) - m * m;
        float sc = rsqrtf(var + 1e-5f) * bn2g[d];
        g_s2[d] = sc;
        g_t2a[d] = bn2b[d] - m * sc;
    }
}

// =====================================================================
// K3: out2 = ksum @ Wck^T (K=512) ; out3 = bn2(xq) @ Wc^T (K=1024).  grid = 192 x 256
__global__ void __launch_bounds__(256, 4)
k3_kernel(float* __restrict__ out2, float* __restrict__ out3)
{
    int blk = blockIdx.x;
    if (blk < 64) {
        // out2: 16 n-stripes x 4 K-splits (chunk 128)
        int n0 = (blk & 15) * 32, s = blk >> 4;
        gemm128<0>(g_ksum, DKIN, g_Wck, DKIN, out2, DOUT, n0, s * 128, 8, nullptr, nullptr);
    } else {
        // out3: 16 n-stripes x 8 K-splits (chunk 128)
        int id = blk - 64;
        int n0 = (id & 15) * 32, s = id >> 4;
        gemm128<2>(g_xq, HD, g_Wc, HD, out3, DOUT, n0, s * 128, 8, g_s2, g_t2a);
    }
}

// =====================================================================
extern "C" void kernel_launch(void* const* d_in, const int* in_sizes, int n_in,
                              void* d_out, int out_size) {
    const float* x    = (const float*)d_in[0];
    const float* k    = (const float*)d_in[1];
    const float* bn1g = (const float*)d_in[2];
    const float* bn1b = (const float*)d_in[3];
    const float* Wx   = (const float*)d_in[4];
    const float* bx   = (const float*)d_in[5];
    const float* Wk   = (const float*)d_in[6];
    const float* bk   = (const float*)d_in[7];
    const float* bn2g = (const float*)d_in[8];
    const float* bn2b = (const float*)d_in[9];
    const float* Wlin = (const float*)d_in[10];
    const float* blin = (const float*)d_in[11];
    const float* Wo   = (const float*)d_in[12];
    const float* bo   = (const float*)d_in[13];
    float* out = (float*)d_out;

    float* attn_out = out;                       // (128,16,1024) == all ones
    float* out2 = out + (size_t)BB * NH * NKK;   // (128,512)
    float* out3 = out2 + (size_t)BB * DOUT;      // (128,512)

    k0_kernel<<<608, 256>>>(x, bn1g, bn1b, Wo, bk, blin, bo, bx);
    k1_kernel<<<2816, 256>>>(x, k, Wx, Wk, Wlin, Wo, (float4*)attn_out, out2, out3);
    k2_kernel<<<64, 256>>>(bn2g, bn2b);
    k3_kernel<<<192, 256>>>(out2, out3);

    (void)in_sizes; (void)n_in; (void)out_size;
}

// round 10
// speedup vs baseline: 1.2716x; 1.2716x over previous
#include <cuda_runtime.h>

#define BB    128
#define DX    1024
#define NKK   1024
#define DKIN  512
#define NH    16
#define DKH   64
#define HD    1024
#define DOUT  512

// ---------------- scratch (device globals; 16B aligned) ----------------
__device__ __align__(16) float g_ksum[BB * DKIN];
__device__ __align__(16) float g_s1[DX], g_t1[DX];     // bn1 affine fold
__device__ __align__(16) float g_xq[BB * HD];
__device__ __align__(16) float g_s2[DKH], g_t2a[DKH];  // bn2 affine fold
__device__ __align__(16) float g_t2buf[BB * HD];       // ksum @ Wk^T
__device__ __align__(16) float g_Wc[DOUT * HD];        // Wo . blockdiag(Wlin^T)
__device__ __align__(16) float g_bias2[DOUT], g_bias3[DOUT];

// =====================================================================
// OLD 128x32 GEMM tile (4x4/thread) — used only for the shadowed xq GEMM in k1.
// MODE: 1 = per-col affine (idx = col-kStart, chunk<=128)
template <int MODE>
__device__ __forceinline__ void gemm128(
    const float* __restrict__ A, int lda,
    const float* __restrict__ W, int ldw,
    float* __restrict__ C, int ldc,
    int n0, int kStart, int nIter,
    const float* __restrict__ gsc, const float* __restrict__ gsh)
{
    __shared__ float As[2][16][132];
    __shared__ float Ws[2][16][36];
    __shared__ float ssc[128], ssh[128];
    const int t = threadIdx.x;
    if (MODE == 1) { if (t < 128) { ssc[t] = gsc[kStart + t]; ssh[t] = gsh[kStart + t]; } }
    if (MODE) __syncthreads();

    const int rowA = t & 127, kgA = t >> 7;
    const int nW = t & 31, kgW = t >> 5;
    const int ty = t >> 3, tx = t & 7;

    float4 ra0, ra1, rw;
    {
        int k0 = kStart;
        ra0 = *(const float4*)&A[(size_t)rowA * lda + k0 + kgA * 4];
        ra1 = *(const float4*)&A[(size_t)rowA * lda + k0 + (kgA + 2) * 4];
        if (t < 128) rw = *(const float4*)&W[(size_t)(n0 + nW) * ldw + k0 + kgW * 4];
        float va[8] = {ra0.x, ra0.y, ra0.z, ra0.w, ra1.x, ra1.y, ra1.z, ra1.w};
        #pragma unroll
        for (int u = 0; u < 2; u++) {
            int kg = kgA + u * 2;
            #pragma unroll
            for (int j = 0; j < 4; j++) {
                float v = va[u * 4 + j];
                if (MODE == 1) { int ci = kg * 4 + j; v = v * ssc[ci] + ssh[ci]; }
                As[0][kg * 4 + j][rowA] = v;
            }
        }
        if (t < 128) {
            Ws[0][kgW * 4 + 0][nW] = rw.x; Ws[0][kgW * 4 + 1][nW] = rw.y;
            Ws[0][kgW * 4 + 2][nW] = rw.z; Ws[0][kgW * 4 + 3][nW] = rw.w;
        }
    }
    __syncthreads();

    float acc[4][4] = {};
    for (int it = 0; it < nIter; it++) {
        const int buf = it & 1;
        float4 na0, na1, nw;
        const bool more = (it + 1 < nIter);
        if (more) {
            int kn = kStart + (it + 1) * 16;
            na0 = *(const float4*)&A[(size_t)rowA * lda + kn + kgA * 4];
            na1 = *(const float4*)&A[(size_t)rowA * lda + kn + (kgA + 2) * 4];
            if (t < 128) nw = *(const float4*)&W[(size_t)(n0 + nW) * ldw + kn + kgW * 4];
        }
        #pragma unroll
        for (int kk = 0; kk < 16; kk++) {
            float4 a = *(const float4*)&As[buf][kk][ty * 4];
            float4 b = *(const float4*)&Ws[buf][kk][tx * 4];
            acc[0][0] += a.x * b.x; acc[0][1] += a.x * b.y; acc[0][2] += a.x * b.z; acc[0][3] += a.x * b.w;
            acc[1][0] += a.y * b.x; acc[1][1] += a.y * b.y; acc[1][2] += a.y * b.z; acc[1][3] += a.y * b.w;
            acc[2][0] += a.z * b.x; acc[2][1] += a.z * b.y; acc[2][2] += a.z * b.z; acc[2][3] += a.z * b.w;
            acc[3][0] += a.w * b.x; acc[3][1] += a.w * b.y; acc[3][2] += a.w * b.z; acc[3][3] += a.w * b.w;
        }
        if (more) {
            int kn = kStart + (it + 1) * 16;
            int nb = buf ^ 1;
            float va[8] = {na0.x, na0.y, na0.z, na0.w, na1.x, na1.y, na1.z, na1.w};
            #pragma unroll
            for (int u = 0; u < 2; u++) {
                int kg = kgA + u * 2;
                #pragma unroll
                for (int j = 0; j < 4; j++) {
                    float v = va[u * 4 + j];
                    if (MODE == 1) { int ci = (kn - kStart) + kg * 4 + j; v = v * ssc[ci] + ssh[ci]; }
                    As[nb][kg * 4 + j][rowA] = v;
                }
            }
            if (t < 128) {
                Ws[nb][kgW * 4 + 0][nW] = nw.x; Ws[nb][kgW * 4 + 1][nW] = nw.y;
                Ws[nb][kgW * 4 + 2][nW] = nw.z; Ws[nb][kgW * 4 + 3][nW] = nw.w;
            }
            __syncthreads();
        }
    }
    #pragma unroll
    for (int i = 0; i < 4; i++)
        #pragma unroll
        for (int j = 0; j < 4; j++)
            atomicAdd(&C[(size_t)(ty * 4 + i) * ldc + n0 + tx * 4 + j], acc[i][j]);
}

// =====================================================================
// NEW 128x64 GEMM tile, 8x4 per thread, double-buffered, atomic epilogue.
// 3 LDS.128 per 32 FFMA -> FFMA-bound. MODE: 0 none; 2 affine idx = col&63.
template <int MODE>
__device__ __forceinline__ void gemmBig(
    const float* __restrict__ A, int lda,
    const float* __restrict__ W, int ldw,
    float* __restrict__ C, int ldc,
    int n0, int kStart, int nIter,
    const float* __restrict__ gsc, const float* __restrict__ gsh)
{
    __shared__ float As[2][16][132];
    __shared__ float Ws[2][16][68];
    __shared__ float ssc[64], ssh[64];
    const int t = threadIdx.x;
    if (MODE == 2) { if (t < 64) { ssc[t] = gsc[t]; ssh[t] = gsh[t]; } __syncthreads(); }

    const int rowA = t & 127, kgA = t >> 7;   // kgA in {0,1}; second A load at kgA+2
    const int nW = t & 63, kgW = t >> 6;      // one float4 of W per thread
    const int ty = t >> 4, tx = t & 15;       // 8 rows x 4 cols per thread

    float4 ra0, ra1, rw;
    {
        int k0 = kStart;
        ra0 = *(const float4*)&A[(size_t)rowA * lda + k0 + kgA * 4];
        ra1 = *(const float4*)&A[(size_t)rowA * lda + k0 + (kgA + 2) * 4];
        rw  = *(const float4*)&W[(size_t)(n0 + nW) * ldw + k0 + kgW * 4];
        float va[8] = {ra0.x, ra0.y, ra0.z, ra0.w, ra1.x, ra1.y, ra1.z, ra1.w};
        #pragma unroll
        for (int u = 0; u < 2; u++) {
            int kg = kgA + u * 2;
            #pragma unroll
            for (int j = 0; j < 4; j++) {
                float v = va[u * 4 + j];
                if (MODE == 2) { int ci = (k0 + kg * 4 + j) & 63; v = v * ssc[ci] + ssh[ci]; }
                As[0][kg * 4 + j][rowA] = v;
            }
        }
        Ws[0][kgW * 4 + 0][nW] = rw.x; Ws[0][kgW * 4 + 1][nW] = rw.y;
        Ws[0][kgW * 4 + 2][nW] = rw.z; Ws[0][kgW * 4 + 3][nW] = rw.w;
    }
    __syncthreads();

    float acc[8][4] = {};
    for (int it = 0; it < nIter; it++) {
        const int buf = it & 1;
        float4 na0, na1, nw;
        const bool more = (it + 1 < nIter);
        if (more) {
            int kn = kStart + (it + 1) * 16;
            na0 = *(const float4*)&A[(size_t)rowA * lda + kn + kgA * 4];
            na1 = *(const float4*)&A[(size_t)rowA * lda + kn + (kgA + 2) * 4];
            nw  = *(const float4*)&W[(size_t)(n0 + nW) * ldw + kn + kgW * 4];
        }
        #pragma unroll
        for (int kk = 0; kk < 16; kk++) {
            float4 a0 = *(const float4*)&As[buf][kk][ty * 8];
            float4 a1 = *(const float4*)&As[buf][kk][ty * 8 + 4];
            float4 b  = *(const float4*)&Ws[buf][kk][tx * 4];
            acc[0][0] += a0.x * b.x; acc[0][1] += a0.x * b.y; acc[0][2] += a0.x * b.z; acc[0][3] += a0.x * b.w;
            acc[1][0] += a0.y * b.x; acc[1][1] += a0.y * b.y; acc[1][2] += a0.y * b.z; acc[1][3] += a0.y * b.w;
            acc[2][0] += a0.z * b.x; acc[2][1] += a0.z * b.y; acc[2][2] += a0.z * b.z; acc[2][3] += a0.z * b.w;
            acc[3][0] += a0.w * b.x; acc[3][1] += a0.w * b.y; acc[3][2] += a0.w * b.z; acc[3][3] += a0.w * b.w;
            acc[4][0] += a1.x * b.x; acc[4][1] += a1.x * b.y; acc[4][2] += a1.x * b.z; acc[4][3] += a1.x * b.w;
            acc[5][0] += a1.y * b.x; acc[5][1] += a1.y * b.y; acc[5][2] += a1.y * b.z; acc[5][3] += a1.y * b.w;
            acc[6][0] += a1.z * b.x; acc[6][1] += a1.z * b.y; acc[6][2] += a1.z * b.z; acc[6][3] += a1.z * b.w;
            acc[7][0] += a1.w * b.x; acc[7][1] += a1.w * b.y; acc[7][2] += a1.w * b.z; acc[7][3] += a1.w * b.w;
        }
        if (more) {
            int kn = kStart + (it + 1) * 16;
            int nb = buf ^ 1;
            float va[8] = {na0.x, na0.y, na0.z, na0.w, na1.x, na1.y, na1.z, na1.w};
            #pragma unroll
            for (int u = 0; u < 2; u++) {
                int kg = kgA + u * 2;
                #pragma unroll
                for (int j = 0; j < 4; j++) {
                    float v = va[u * 4 + j];
                    if (MODE == 2) { int ci = (kn + kg * 4 + j) & 63; v = v * ssc[ci] + ssh[ci]; }
                    As[nb][kg * 4 + j][rowA] = v;
                }
            }
            Ws[nb][kgW * 4 + 0][nW] = nw.x; Ws[nb][kgW * 4 + 1][nW] = nw.y;
            Ws[nb][kgW * 4 + 2][nW] = nw.z; Ws[nb][kgW * 4 + 3][nW] = nw.w;
            __syncthreads();
        }
    }
    #pragma unroll
    for (int i = 0; i < 8; i++)
        #pragma unroll
        for (int j = 0; j < 4; j++)
            atomicAdd(&C[(size_t)(ty * 8 + i) * ldc + n0 + tx * 4 + j], acc[i][j]);
}

// =====================================================================
// classic 64x64 tile, direct store (Wc only; runs in k1 shadow)
__device__ __forceinline__ void gemm64(
    const float* __restrict__ A, int lda,
    const float* __restrict__ B, int ldb,
    float* __restrict__ C, int ldc,
    int m0, int n0B, int n0C, int kStart, int kLen)
{
    __shared__ float As[16][68];
    __shared__ float Bs[16][68];
    int t = threadIdx.x;
    int ty = t >> 4, tx = t & 15;
    float acc[4][4] = {};
    for (int k0 = kStart; k0 < kStart + kLen; k0 += 16) {
        {
            int m = t & 63, kg = t >> 6;
            float4 a = *(const float4*)&A[(size_t)(m0 + m) * lda + k0 + kg * 4];
            As[kg * 4 + 0][m] = a.x; As[kg * 4 + 1][m] = a.y;
            As[kg * 4 + 2][m] = a.z; As[kg * 4 + 3][m] = a.w;
        }
        {
            int n4 = t & 15, kk = t >> 4;
            float4 b = *(const float4*)&B[(size_t)(k0 + kk) * ldb + n0B + n4 * 4];
            *(float4*)&Bs[kk][n4 * 4] = b;
        }
        __syncthreads();
        #pragma unroll
        for (int kk = 0; kk < 16; kk++) {
            float4 a = *(const float4*)&As[kk][ty * 4];
            float4 b = *(const float4*)&Bs[kk][tx * 4];
            acc[0][0] += a.x * b.x; acc[0][1] += a.x * b.y; acc[0][2] += a.x * b.z; acc[0][3] += a.x * b.w;
            acc[1][0] += a.y * b.x; acc[1][1] += a.y * b.y; acc[1][2] += a.y * b.z; acc[1][3] += a.y * b.w;
            acc[2][0] += a.z * b.x; acc[2][1] += a.z * b.y; acc[2][2] += a.z * b.z; acc[2][3] += a.z * b.w;
            acc[3][0] += a.w * b.x; acc[3][1] += a.w * b.y; acc[3][2] += a.w * b.z; acc[3][3] += a.w * b.w;
        }
        __syncthreads();
    }
    #pragma unroll
    for (int i = 0; i < 4; i++)
        #pragma unroll
        for (int j = 0; j < 4; j++)
            C[(size_t)(m0 + ty * 4 + i) * ldc + n0C + tx * 4 + j] = acc[i][j];
}

// =====================================================================
// K0: bn1 stats + bias vectors + zero/bias inits.  grid = 480 x 256
__global__ void k0_kernel(const float* __restrict__ x,
                          const float* __restrict__ bn1g, const float* __restrict__ bn1b,
                          const float* __restrict__ Wo,
                          const float* __restrict__ bk, const float* __restrict__ blin,
                          const float* __restrict__ bo, const float* __restrict__ bx)
{
    int blk = blockIdx.x, t = threadIdx.x;
    if (blk < 32) {
        __shared__ float ss[8][32], sq[8][32];
        int c = t & 31, r = t >> 5;
        int col = blk * 32 + c;
        float s = 0.f, q = 0.f;
        for (int i = r; i < BB; i += 8) {
            float v = x[(size_t)i * DX + col];
            s += v; q += v * v;
        }
        ss[r][c] = s; sq[r][c] = q;
        __syncthreads();
        if (r == 0) {
            float S = 0.f, Q = 0.f;
            #pragma unroll
            for (int i = 0; i < 8; i++) { S += ss[i][c]; Q += sq[i][c]; }
            float m = S * (1.f / BB);
            float var = Q * (1.f / BB) - m * m;
            float sc = rsqrtf(var + 1e-5f) * bn1g[col];
            g_s1[col] = sc;
            g_t1[col] = bn1b[col] - m * sc;
        }
    } else if (blk < 160) {
        int wid = (blk - 32) * 8 + (t >> 5), lane = t & 31;
        int o = wid & 511;
        const float* wrow = Wo + (size_t)o * HD;
        float s = 0.f;
        if (wid < 512) {
            for (int j = lane; j < HD; j += 32) s += wrow[j] * bk[j];
        } else {
            for (int j = lane; j < HD; j += 32) s += wrow[j] * blin[j & 63];
        }
        #pragma unroll
        for (int off = 16; off > 0; off >>= 1) s += __shfl_xor_sync(0xffffffffu, s, off);
        if (lane == 0) {
            if (wid < 512) g_bias2[o] = (float)NKK * s + bo[o];
            else           g_bias3[o] = s + bo[o];
        }
    } else if (blk < 288) {
        ((float4*)g_xq)[(size_t)(blk - 160) * 256 + t] = ((const float4*)bx)[t];
    } else if (blk < 352) {
        ((float4*)g_ksum)[(size_t)(blk - 288) * 256 + t] = make_float4(0.f, 0.f, 0.f, 0.f);
    } else {
        ((float4*)g_t2buf)[(size_t)(blk - 352) * 256 + t] = make_float4(0.f, 0.f, 0.f, 0.f);
    }
}

// =====================================================================
// K1: HBM-bound ksum + xq GEMM + Wc + fills.  grid = 2560 x 256 (= round 8)
__global__ void __launch_bounds__(256, 4)
k1_kernel(const float* __restrict__ x, const float* __restrict__ k,
          const float* __restrict__ Wx, const float* __restrict__ Wlin,
          const float* __restrict__ Wo,
          float4* __restrict__ attn_out,
          float* __restrict__ out2, float* __restrict__ out3)
{
    int blk = blockIdx.x, t = threadIdx.x;
    int ksumIdx = (blk < 512) ? blk : ((blk >= 768 && blk < 1280) ? blk - 256 : -1);
    if (ksumIdx >= 0) {
        int b = ksumIdx >> 3, chunk = ksumIdx & 7;
        int c4 = t & 127, h = t >> 7;
        const float4* kp = (const float4*)(k + (size_t)b * NKK * DKIN
                                             + (size_t)chunk * 128 * DKIN);
        float4 acc = make_float4(0.f, 0.f, 0.f, 0.f);
        int base = h * 64;
        #pragma unroll 8
        for (int n = 0; n < 64; n++) {
            float4 v = kp[(size_t)(base + n) * (DKIN / 4) + c4];
            acc.x += v.x; acc.y += v.y; acc.z += v.z; acc.w += v.w;
        }
        __shared__ float4 sbuf[128];
        if (h) sbuf[c4] = acc;
        __syncthreads();
        if (!h) {
            float4 o = sbuf[c4];
            float* dst = &g_ksum[(size_t)b * DKIN + c4 * 4];
            atomicAdd(dst + 0, acc.x + o.x); atomicAdd(dst + 1, acc.y + o.y);
            atomicAdd(dst + 2, acc.z + o.z); atomicAdd(dst + 3, acc.w + o.w);
        }
    } else if (blk < 768) {
        int id = blk - 512;
        int n0 = (id & 31) * 32, s = id >> 5;
        gemm128<1>(x, DX, Wx, DX, g_xq, HD, n0, s * 128, 8, g_s1, g_t1);
    } else if (blk < 1408) {
        int id = blk - 1280;
        int h = id >> 3, ms = id & 7;
        gemm64(Wo + h * 64, HD, Wlin, DKH, g_Wc, HD, ms * 64, 0, h * 64, 0, 64);
    } else if (blk < 2432) {
        size_t base = (size_t)(blk - 1408) * 512 + t * 2;
        float4 one = make_float4(1.f, 1.f, 1.f, 1.f);
        attn_out[base] = one; attn_out[base + 1] = one;
    } else {
        int idx = (blk - 2432) * 1024 + t * 4;
        if (idx < BB * DOUT) {
            *(float4*)&out2[idx] = *(const float4*)&g_bias2[idx & (DOUT - 1)];
        } else {
            int i2 = idx - BB * DOUT;
            *(float4*)&out3[i2] = *(const float4*)&g_bias3[i2 & (DOUT - 1)];
        }
    }
}

// =====================================================================
// K2: bn2 stats + t2 = ksum @ Wk^T.  grid = 192 x 256
__global__ void __launch_bounds__(256, 3)
k2_kernel(const float* __restrict__ bn2g, const float* __restrict__ bn2b,
          const float* __restrict__ Wk)
{
    int blk = blockIdx.x, t = threadIdx.x;
    if (blk < 64) {
        __shared__ float ss[256], sq[256];
        int d = blk;
        float s = 0.f, q = 0.f;
        for (int i = t; i < BB * NH; i += 256) {
            int b = i >> 4, h = i & 15;
            float v = g_xq[(size_t)b * HD + h * DKH + d];
            s += v; q += v * v;
        }
        ss[t] = s; sq[t] = q;
        __syncthreads();
        for (int o = 128; o > 0; o >>= 1) {
            if (t < o) { ss[t] += ss[t + o]; sq[t] += sq[t + o]; }
            __syncthreads();
        }
        if (t == 0) {
            float m = ss[0] * (1.f / (BB * NH));
            float var = sq[0] * (1.f / (BB * NH)) - m * m;
            float sc = rsqrtf(var + 1e-5f) * bn2g[d];
            g_s2[d] = sc;
            g_t2a[d] = bn2b[d] - m * sc;
        }
    } else {
        // t2 += ksum @ Wk^T : 16 n-tiles(64) x 8 K-splits (chunk 64) = 128 blocks
        int id = blk - 64;
        int n0 = (id & 15) * 64, s = id >> 4;
        gemmBig<0>(g_ksum, DKIN, Wk, DKIN, g_t2buf, HD, n0, s * 64, 4, nullptr, nullptr);
    }
}

// =====================================================================
// K3: out2 = t2 @ Wo^T ; out3 = bn2(xq) @ Wc^T.  grid = 128 x 256
__global__ void __launch_bounds__(256, 3)
k3_kernel(const float* __restrict__ Wo, float* __restrict__ out2, float* __restrict__ out3)
{
    int blk = blockIdx.x;
    if (blk < 64) {
        // out2: 8 n-tiles(64) x 8 K-splits (chunk 128)
        int n0 = (blk & 7) * 64, s = blk >> 3;
        gemmBig<0>(g_t2buf, HD, Wo, HD, out2, DOUT, n0, s * 128, 8, nullptr, nullptr);
    } else {
        int id = blk - 64;
        int n0 = (id & 7) * 64, s = id >> 3;
        gemmBig<2>(g_xq, HD, g_Wc, HD, out3, DOUT, n0, s * 128, 8, g_s2, g_t2a);
    }
}

// =====================================================================
extern "C" void kernel_launch(void* const* d_in, const int* in_sizes, int n_in,
                              void* d_out, int out_size) {
    const float* x    = (const float*)d_in[0];
    const float* k    = (const float*)d_in[1];
    const float* bn1g = (const float*)d_in[2];
    const float* bn1b = (const float*)d_in[3];
    const float* Wx   = (const float*)d_in[4];
    const float* bx   = (const float*)d_in[5];
    const float* Wk   = (const float*)d_in[6];
    const float* bk   = (const float*)d_in[7];
    const float* bn2g = (const float*)d_in[8];
    const float* bn2b = (const float*)d_in[9];
    const float* Wlin = (const float*)d_in[10];
    const float* blin = (const float*)d_in[11];
    const float* Wo   = (const float*)d_in[12];
    const float* bo   = (const float*)d_in[13];
    float* out = (float*)d_out;

    float* attn_out = out;                       // (128,16,1024) == all ones
    float* out2 = out + (size_t)BB * NH * NKK;   // (128,512)
    float* out3 = out2 + (size_t)BB * DOUT;      // (128,512)

    k0_kernel<<<480, 256>>>(x, bn1g, bn1b, Wo, bk, blin, bo, bx);
    k1_kernel<<<2560, 256>>>(x, k, Wx, Wlin, Wo, (float4*)attn_out, out2, out3);
    k2_kernel<<<192, 256>>>(bn2g, bn2b, Wk);
    k3_kernel<<<128, 256>>>(Wo, out2, out3);

    (void)in_sizes; (void)n_in; (void)out_size;
}